// round 8
// baseline (speedup 1.0000x reference)
#include <cuda_runtime.h>
#include <cuda_fp16.h>
#include <cstdint>

// ============================================================================
// Problem constants (dataset: n1=n2=8192, d=256)
// ============================================================================
#define D_DIM 256
#define N_MAX 8192
#define SQRT3F 1.7320508075688772f
#define LO_SCALE 16384.0f           // 2^14 : lo-limb pre-scale into e4m3 range
#define LO_DESCALE 6.103515625e-05f // 2^-14

// Scratch (allocation-free rule: __device__ globals)
__device__ __align__(128) __half  g_ah[N_MAX * D_DIM];   // hi limb fp16 (x1)
__device__ __align__(128) __half  g_bh[N_MAX * D_DIM];   // hi limb fp16 (x2)
__device__ __align__(128) uint8_t g_a8h[N_MAX * D_DIM];  // hi limb e4m3
__device__ __align__(128) uint8_t g_a8l[N_MAX * D_DIM];  // lo limb * 2^14 e4m3
__device__ __align__(128) uint8_t g_b8h[N_MAX * D_DIM];
__device__ __align__(128) uint8_t g_b8l[N_MAX * D_DIM];
__device__ __align__(128) float   g_sq1[N_MAX];
__device__ __align__(128) float   g_sq2[N_MAX];
__device__ __align__(128) float   g_part[32 * D_DIM];
__device__ __align__(128) float   g_adj[D_DIM];
__device__ __align__(128) float   g_rls[D_DIM];

__device__ __forceinline__ uint32_t h2_to_u32(__half2 h) {
    union { __half2 h; uint32_t u; } c; c.h = h; return c.u;
}
__device__ __forceinline__ __half2 u32_to_h2(uint32_t u) {
    union { uint32_t u; __half2 h; } c; c.u = u; return c.h;
}

// e4m3 pair conversion: low byte <- lo, high byte <- hi
__device__ __forceinline__ uint16_t f2_to_e4m3x2(float lo, float hi) {
    uint16_t r;
    asm("cvt.rn.satfinite.e4m3x2.f32 %0, %1, %2;" : "=h"(r) : "f"(hi), "f"(lo));
    return r;
}

// ============================================================================
// Portable PTX helpers (sm_80/89-era ISA: cp.async / ldmatrix / mma.sync)
// ============================================================================
__device__ __forceinline__ uint32_t smem_u32(const void* p) {
    uint32_t a;
    asm("{ .reg .u64 t; cvta.to.shared.u64 t, %1; cvt.u32.u64 %0, t; }"
        : "=r"(a) : "l"(p));
    return a;
}

__device__ __forceinline__ void cp16(uint32_t dst, const void* src) {
    asm volatile("cp.async.cg.shared.global [%0], [%1], 16;"
                 :: "r"(dst), "l"(src) : "memory");
}
#define CP_COMMIT() asm volatile("cp.async.commit_group;" ::: "memory")
#define CP_WAIT1()  asm volatile("cp.async.wait_group 1;" ::: "memory")

#define LDSM_X4(r, addr) \
    asm volatile("ldmatrix.sync.aligned.m8n8.x4.shared.b16 {%0,%1,%2,%3}, [%4];" \
                 : "=r"((r)[0]), "=r"((r)[1]), "=r"((r)[2]), "=r"((r)[3]) \
                 : "r"(addr))

// fp16 x fp16 -> fp32 accum (main hh pass)
__device__ __forceinline__ void mma16816_f32(float* c, const uint32_t* a,
                                             const uint32_t* b) {
    asm volatile(
        "mma.sync.aligned.m16n8k16.row.col.f32.f16.f16.f32 "
        "{%0,%1,%2,%3}, {%4,%5,%6,%7}, {%8,%9}, {%0,%1,%2,%3};"
        : "+f"(c[0]), "+f"(c[1]), "+f"(c[2]), "+f"(c[3])
        : "r"(a[0]), "r"(a[1]), "r"(a[2]), "r"(a[3]),
          "r"(b[0]), "r"(b[1]));
}

// e4m3 x e4m3 -> fp16 accum, k32 (cross-term passes)
__device__ __forceinline__ void mma_fp8_f16(uint32_t* c, const uint32_t* a,
                                            const uint32_t* b) {
    asm volatile(
        "mma.sync.aligned.m16n8k32.row.col.f16.e4m3.e4m3.f16 "
        "{%0,%1}, {%2,%3,%4,%5}, {%6,%7}, {%0,%1};"
        : "+r"(c[0]), "+r"(c[1])
        : "r"(a[0]), "r"(a[1]), "r"(a[2]), "r"(a[3]),
          "r"(b[0]), "r"(b[1]));
}

// ============================================================================
// Prep kernels (exactly 3 launches before the GEMM -> ncu -s5 hits the GEMM)
// ============================================================================
__global__ void k_mean_partial(const float* __restrict__ x1, int n1) {
    int d = threadIdx.x, b = blockIdx.x;
    float s = 0.f;
    for (int r = b; r < n1; r += 32) s += x1[(size_t)r * D_DIM + d];
    g_part[b * D_DIM + d] = s;
}

__global__ void k_mean_final(const float* __restrict__ ls, int n1) {
    int d = threadIdx.x;
    float s = 0.f;
#pragma unroll
    for (int b = 0; b < 32; b++) s += g_part[b * D_DIM + d];
    g_adj[d] = s / (float)n1;
    g_rls[d] = 1.0f / ls[d];
}

// Center, scale, split fp32 -> fp16 hi + e4m3(hi) + e4m3(lo*2^14); row sqnorm.
// One warp per row; covers x1 rows [0,n1) and x2 rows [n1,ntot).
__global__ void k_normalize2(const float* __restrict__ x1,
                             const float* __restrict__ x2, int n1, int ntot) {
    int wid  = threadIdx.x >> 5;
    int lane = threadIdx.x & 31;
    int grow = blockIdx.x * 8 + wid;
    if (grow >= ntot) return;

    int which = (grow >= n1);
    int row   = which ? (grow - n1) : grow;
    const float* x = which ? x2 : x1;
    __half*  hi  = which ? g_bh  : g_ah;
    uint8_t* q8h = which ? g_b8h : g_a8h;
    uint8_t* q8l = which ? g_b8l : g_a8l;
    float*   sq  = which ? g_sq2 : g_sq1;

    const float4* xr = reinterpret_cast<const float4*>(x + (size_t)row * D_DIM);
    const float4* aj = reinterpret_cast<const float4*>(g_adj);
    const float4* rl = reinterpret_cast<const float4*>(g_rls);

    float ssum = 0.f;
    uint4 packh;                       // 8 fp16
    uint32_t* ph = reinterpret_cast<uint32_t*>(&packh);
    uint16_t p8h[4], p8l[4];           // 8 e4m3 each
#pragma unroll
    for (int g = 0; g < 2; g++) {
        int v4 = lane * 2 + g;
        float4 xv = xr[v4];
        float4 av = aj[v4];
        float4 rv = rl[v4];
        float vv[4] = { (xv.x - av.x) * rv.x, (xv.y - av.y) * rv.y,
                        (xv.z - av.z) * rv.z, (xv.w - av.w) * rv.w };
#pragma unroll
        for (int e = 0; e < 4; e += 2) {
            float v0 = vv[e], v1 = vv[e + 1];
            __half h0 = __float2half_rn(v0);
            __half h1 = __float2half_rn(v1);
            float  f0 = __half2float(h0);
            float  f1 = __half2float(h1);
            float  l0 = v0 - f0;
            float  l1 = v1 - f1;
            ph[g * 2 + e / 2]  = h2_to_u32(__halves2half2(h0, h1));
            p8h[g * 2 + e / 2] = f2_to_e4m3x2(f0, f1);
            p8l[g * 2 + e / 2] = f2_to_e4m3x2(l0 * LO_SCALE, l1 * LO_SCALE);
            ssum = fmaf(v0, v0, ssum);
            ssum = fmaf(v1, v1, ssum);
        }
    }
    reinterpret_cast<uint4*>(hi + (size_t)row * D_DIM)[lane] = packh;
    uint2 u8h = make_uint2((uint32_t)p8h[0] | ((uint32_t)p8h[1] << 16),
                           (uint32_t)p8h[2] | ((uint32_t)p8h[3] << 16));
    uint2 u8l = make_uint2((uint32_t)p8l[0] | ((uint32_t)p8l[1] << 16),
                           (uint32_t)p8l[2] | ((uint32_t)p8l[3] << 16));
    reinterpret_cast<uint2*>(q8h + (size_t)row * D_DIM)[lane] = u8h;
    reinterpret_cast<uint2*>(q8l + (size_t)row * D_DIM)[lane] = u8l;
#pragma unroll
    for (int o = 16; o > 0; o >>= 1)
        ssum += __shfl_xor_sync(0xffffffffu, ssum, o);
    if (lane == 0) sq[row] = ssum;
}

// ============================================================================
// Fused GEMM + Matern epilogue
//
// CTA 128x128, 4 warps (2x2), warp tile 64x64, occ 2 (8 warps/SM).
// K = 256 in 8 chunks of 32, cp.async double-buffered (R6 structure).
// Per k32 chunk per warp:
//   64 fp16 HMMA   : hh, fp32 accum (precision-critical)
//   64 fp8  MMA k32: ah8*bl8s + al8s*bh8, fp16 accum (6%-accuracy correction)
// ============================================================================
#define ROW_H    80                      // fp16 tile row stride (64B data + pad)
#define TILE_H   (128 * ROW_H)           // 10240
#define ROW_Q    48                      // fp8 tile row stride (32B data + pad)
#define TILE_Q   (128 * ROW_Q)           // 6144
#define OFF_AH   0
#define OFF_BH   TILE_H
#define OFF_A8H  (2 * TILE_H)
#define OFF_A8L  (2 * TILE_H + TILE_Q)
#define OFF_B8H  (2 * TILE_H + 2 * TILE_Q)
#define OFF_B8L  (2 * TILE_H + 3 * TILE_Q)
#define STAGE_B  (2 * TILE_H + 4 * TILE_Q)   // 45056
#define SMEM_REQ (2 * STAGE_B + 1536)

__global__ void __launch_bounds__(128, 2)
k_matern_gemm(float* __restrict__ out, int n2) {
    extern __shared__ char smem_raw[];
    uint32_t sbase_u = smem_u32(smem_raw);
    uint32_t abase = (sbase_u + 127u) & ~127u;
    char* ap = smem_raw + (abase - sbase_u);

    const int tid  = threadIdx.x;
    const int lane = tid & 31;
    const int wid  = tid >> 5;
    const int wm   = wid >> 1;   // 0..1 : 64-row slice
    const int wn   = wid & 1;    // 0..1 : 64-col slice
    const int bX   = blockIdx.x;
    const int bY   = blockIdx.y;

    float* s_sq1 = reinterpret_cast<float*>(ap + 2 * STAGE_B);
    float* s_sq2 = reinterpret_cast<float*>(ap + 2 * STAGE_B + 512);
    s_sq1[tid] = g_sq1[(size_t)bY * 128 + tid];
    s_sq2[tid] = g_sq2[(size_t)bX * 128 + tid];

    const __half*  __restrict__ pAh  = g_ah  + (size_t)bY * 128 * D_DIM;
    const __half*  __restrict__ pBh  = g_bh  + (size_t)bX * 128 * D_DIM;
    const uint8_t* __restrict__ pA8h = g_a8h + (size_t)bY * 128 * D_DIM;
    const uint8_t* __restrict__ pA8l = g_a8l + (size_t)bY * 128 * D_DIM;
    const uint8_t* __restrict__ pB8h = g_b8h + (size_t)bX * 128 * D_DIM;
    const uint8_t* __restrict__ pB8l = g_b8l + (size_t)bX * 128 * D_DIM;

    // one k32 chunk: fp16 2x512 cp16, fp8 4x256 cp16 -> 16 cp16/thread
    auto load_stage = [&](int buf, int kc) {
        uint32_t sbuf = abase + (uint32_t)buf * STAGE_B;
        // fp16 tiles: 64B per row-chunk = 4 segs
#pragma unroll
        for (int i = 0; i < 4; i++) {
            int idx = tid + i * 128;             // 0..511
            int row = idx >> 2;
            int seg = idx & 3;
            cp16(sbuf + OFF_AH + (uint32_t)(row * ROW_H + seg * 16),
                 pAh + (size_t)row * D_DIM + kc * 32 + seg * 8);
            cp16(sbuf + OFF_BH + (uint32_t)(row * ROW_H + seg * 16),
                 pBh + (size_t)row * D_DIM + kc * 32 + seg * 8);
        }
        // fp8 tiles: 32B per row-chunk = 2 segs
#pragma unroll
        for (int i = 0; i < 2; i++) {
            int idx = tid + i * 128;             // 0..255
            int row = idx >> 1;
            int seg = idx & 1;
            uint32_t doff = (uint32_t)(row * ROW_Q + seg * 16);
            size_t   soff = (size_t)row * D_DIM + kc * 32 + seg * 16;
            cp16(sbuf + OFF_A8H + doff, pA8h + soff);
            cp16(sbuf + OFF_A8L + doff, pA8l + soff);
            cp16(sbuf + OFF_B8H + doff, pB8h + soff);
            cp16(sbuf + OFF_B8L + doff, pB8l + soff);
        }
    };

    float acc[4][8][4];                 // hh fp32
    uint32_t cx[4][8][2];               // cross fp16x2 (scaled by 2^14)
#pragma unroll
    for (int i = 0; i < 4; i++)
#pragma unroll
        for (int j = 0; j < 8; j++) {
#pragma unroll
            for (int e = 0; e < 4; e++) acc[i][j][e] = 0.f;
            cx[i][j][0] = 0u; cx[i][j][1] = 0u;
        }

    load_stage(0, 0);
    CP_COMMIT();

    const int NCHUNK = D_DIM / 32;   // 8
    for (int c = 0; c < NCHUNK; c++) {
        if (c + 1 < NCHUNK) load_stage((c + 1) & 1, c + 1);
        CP_COMMIT();
        CP_WAIT1();
        __syncthreads();

        uint32_t sbuf = abase + (uint32_t)(c & 1) * STAGE_B;
        const int arow = wm * 64 + (lane & 15);
        const int t    = lane >> 3;
        const int bn   = wn * 64 + ((t >> 1) << 3) + (lane & 7);

        // ======== fp16 hh pass: 2 k16 steps ========
#pragma unroll
        for (int s = 0; s < 2; s++) {
            uint32_t ah[4][4], bh[4][4];
            int ag = s * 2 + (lane >> 4);
#pragma unroll
            for (int mt = 0; mt < 4; mt++)
                LDSM_X4(ah[mt], sbuf + OFF_AH +
                        (uint32_t)((arow + mt * 16) * ROW_H + ag * 16));
            int bg = s * 2 + (t & 1);
#pragma unroll
            for (int ng = 0; ng < 4; ng++)
                LDSM_X4(bh[ng], sbuf + OFF_BH +
                        (uint32_t)((bn + ng * 16) * ROW_H + bg * 16));
#pragma unroll
            for (int mt = 0; mt < 4; mt++)
#pragma unroll
                for (int ng = 0; ng < 4; ng++) {
                    mma16816_f32(acc[mt][ng * 2],     ah[mt], bh[ng]);
                    mma16816_f32(acc[mt][ng * 2 + 1], ah[mt], bh[ng] + 2);
                }
        }

        // ======== fp8 cross pass 1: ah8 * bl8s ========
        {
            uint32_t a8[4][4], b8[4][4];
            int ag8 = lane >> 4;            // 16B seg of 32B row
            int bg8 = t & 1;
#pragma unroll
            for (int mt = 0; mt < 4; mt++)
                LDSM_X4(a8[mt], sbuf + OFF_A8H +
                        (uint32_t)((arow + mt * 16) * ROW_Q + ag8 * 16));
#pragma unroll
            for (int ng = 0; ng < 4; ng++)
                LDSM_X4(b8[ng], sbuf + OFF_B8L +
                        (uint32_t)((bn + ng * 16) * ROW_Q + bg8 * 16));
#pragma unroll
            for (int mt = 0; mt < 4; mt++)
#pragma unroll
                for (int ng = 0; ng < 4; ng++) {
                    mma_fp8_f16(cx[mt][ng * 2],     a8[mt], b8[ng]);
                    mma_fp8_f16(cx[mt][ng * 2 + 1], a8[mt], b8[ng] + 2);
                }
        }
        // ======== fp8 cross pass 2: al8s * bh8 ========
        {
            uint32_t a8[4][4], b8[4][4];
            int ag8 = lane >> 4;
            int bg8 = t & 1;
#pragma unroll
            for (int mt = 0; mt < 4; mt++)
                LDSM_X4(a8[mt], sbuf + OFF_A8L +
                        (uint32_t)((arow + mt * 16) * ROW_Q + ag8 * 16));
#pragma unroll
            for (int ng = 0; ng < 4; ng++)
                LDSM_X4(b8[ng], sbuf + OFF_B8H +
                        (uint32_t)((bn + ng * 16) * ROW_Q + bg8 * 16));
#pragma unroll
            for (int mt = 0; mt < 4; mt++)
#pragma unroll
                for (int ng = 0; ng < 4; ng++) {
                    mma_fp8_f16(cx[mt][ng * 2],     a8[mt], b8[ng]);
                    mma_fp8_f16(cx[mt][ng * 2 + 1], a8[mt], b8[ng] + 2);
                }
        }
        __syncthreads();
    }

    // ---- fused Matern epilogue: dot = hh + cross * 2^-14 ----
    const int r0 = lane >> 2;
    const int c0 = 2 * (lane & 3);
#pragma unroll
    for (int mt = 0; mt < 4; mt++) {
        int row_l = wm * 64 + mt * 16 + r0;
        int row_g = bY * 128 + row_l;
        float sqa0 = s_sq1[row_l];
        float sqa8 = s_sq1[row_l + 8];
        float* orow0 = out + (size_t)row_g * (size_t)n2 + (size_t)bX * 128;
        float* orow8 = orow0 + 8u * (size_t)n2;
#pragma unroll
        for (int nt = 0; nt < 8; nt++) {
            int col_l = wn * 64 + nt * 8 + c0;
            float sqb0 = s_sq2[col_l];
            float sqb1 = s_sq2[col_l + 1];
            const float* a = acc[mt][nt];
            float2 x0 = __half22float2(u32_to_h2(cx[mt][nt][0]));
            float2 x1 = __half22float2(u32_to_h2(cx[mt][nt][1]));
            float dots[4] = { fmaf(x0.x, LO_DESCALE, a[0]),
                              fmaf(x0.y, LO_DESCALE, a[1]),
                              fmaf(x1.x, LO_DESCALE, a[2]),
                              fmaf(x1.y, LO_DESCALE, a[3]) };
            float sqs[4]  = { sqa0 + sqb0, sqa0 + sqb1, sqa8 + sqb0, sqa8 + sqb1 };
            float res[4];
#pragma unroll
            for (int e = 0; e < 4; e++) {
                float d2 = fmaf(-2.f, dots[e], sqs[e]);
                d2 = fmaxf(d2, 1e-30f);
                float t2 = SQRT3F * (d2 * rsqrtf(d2));
                res[e] = (1.f + t2) * __expf(-t2);
            }
            *reinterpret_cast<float2*>(orow0 + col_l) = make_float2(res[0], res[1]);
            *reinterpret_cast<float2*>(orow8 + col_l) = make_float2(res[2], res[3]);
        }
    }
}

// ============================================================================
// kernel_launch
// ============================================================================
extern "C" void kernel_launch(void* const* d_in, const int* in_sizes, int n_in,
                              void* d_out, int out_size) {
    const float* x1 = (const float*)d_in[0];
    const float* x2 = (const float*)d_in[1];
    const float* ls = (const float*)d_in[2];
    float* out = (float*)d_out;

    int d  = in_sizes[2];            // 256
    int n1 = in_sizes[0] / d;        // 8192
    int n2 = in_sizes[1] / d;        // 8192

    k_mean_partial<<<32, D_DIM>>>(x1, n1);
    k_mean_final<<<1, D_DIM>>>(ls, n1);
    k_normalize2<<<(n1 + n2) / 8, 256>>>(x1, x2, n1, n1 + n2);

    static bool attr_set = false;
    if (!attr_set) {
        cudaFuncSetAttribute(k_matern_gemm,
                             cudaFuncAttributeMaxDynamicSharedMemorySize, SMEM_REQ);
        attr_set = true;
    }
    dim3 grid(n2 / 128, n1 / 128);
    k_matern_gemm<<<grid, 128, SMEM_REQ>>>(out, n2);
}

// round 9
// speedup vs baseline: 1.6841x; 1.6841x over previous
#include <cuda_runtime.h>
#include <cuda_fp16.h>
#include <cstdint>

// ============================================================================
// Problem constants (dataset: n1=n2=8192, d=256)
// ============================================================================
#define D_DIM 256
#define N_MAX 8192
#define SQRT3F 1.7320508075688772f

// Scratch (allocation-free rule: __device__ globals)
// 2-pass scheme: dot = ah*(bh+bl).  A side needs hi limb only; B side hi+lo.
__device__ __align__(128) __half g_ah[N_MAX * D_DIM];
__device__ __align__(128) __half g_bh[N_MAX * D_DIM];
__device__ __align__(128) __half g_bl[N_MAX * D_DIM];
__device__ __align__(128) float  g_sq1[N_MAX];
__device__ __align__(128) float  g_sq2[N_MAX];
__device__ __align__(128) float  g_part[32 * D_DIM];
__device__ __align__(128) float  g_adj[D_DIM];
__device__ __align__(128) float  g_rls[D_DIM];

__device__ __forceinline__ uint32_t h2_to_u32(__half2 h) {
    union { __half2 h; uint32_t u; } c; c.h = h; return c.u;
}

// ============================================================================
// Portable PTX helpers (sm_80-era ISA only: cp.async / ldmatrix / mma.sync)
// ============================================================================
__device__ __forceinline__ uint32_t smem_u32(const void* p) {
    uint32_t a;
    asm("{ .reg .u64 t; cvta.to.shared.u64 t, %1; cvt.u32.u64 %0, t; }"
        : "=r"(a) : "l"(p));
    return a;
}

__device__ __forceinline__ void cp16(uint32_t dst, const void* src) {
    asm volatile("cp.async.cg.shared.global [%0], [%1], 16;"
                 :: "r"(dst), "l"(src) : "memory");
}
#define CP_COMMIT() asm volatile("cp.async.commit_group;" ::: "memory")
#define CP_WAIT1()  asm volatile("cp.async.wait_group 1;" ::: "memory")

#define LDSM_X4(r, addr) \
    asm volatile("ldmatrix.sync.aligned.m8n8.x4.shared.b16 {%0,%1,%2,%3}, [%4];" \
                 : "=r"((r)[0]), "=r"((r)[1]), "=r"((r)[2]), "=r"((r)[3]) \
                 : "r"(addr))

// fp32-accumulator HMMA
__device__ __forceinline__ void mma16816_f32(float* c, const uint32_t* a,
                                             const uint32_t* b) {
    asm volatile(
        "mma.sync.aligned.m16n8k16.row.col.f32.f16.f16.f32 "
        "{%0,%1,%2,%3}, {%4,%5,%6,%7}, {%8,%9}, {%0,%1,%2,%3};"
        : "+f"(c[0]), "+f"(c[1]), "+f"(c[2]), "+f"(c[3])
        : "r"(a[0]), "r"(a[1]), "r"(a[2]), "r"(a[3]),
          "r"(b[0]), "r"(b[1]));
}

// ============================================================================
// Prep kernels (exactly 3 launches before the GEMM -> ncu -s5 hits the GEMM)
// ============================================================================
__global__ void k_mean_partial(const float* __restrict__ x1, int n1) {
    int d = threadIdx.x, b = blockIdx.x;
    float s = 0.f;
    for (int r = b; r < n1; r += 32) s += x1[(size_t)r * D_DIM + d];
    g_part[b * D_DIM + d] = s;
}

__global__ void k_mean_final(const float* __restrict__ ls, int n1) {
    int d = threadIdx.x;
    float s = 0.f;
#pragma unroll
    for (int b = 0; b < 32; b++) s += g_part[b * D_DIM + d];
    g_adj[d] = s / (float)n1;
    g_rls[d] = 1.0f / ls[d];
}

// Center, scale, split; row sqnorm from EXACT fp32 values.
// x1 rows: hi limb only. x2 rows: hi + lo limbs.
__global__ void k_normalize2(const float* __restrict__ x1,
                             const float* __restrict__ x2, int n1, int ntot) {
    int wid  = threadIdx.x >> 5;
    int lane = threadIdx.x & 31;
    int grow = blockIdx.x * 8 + wid;
    if (grow >= ntot) return;

    int which = (grow >= n1);
    int row   = which ? (grow - n1) : grow;
    const float* x = which ? x2 : x1;
    __half* hi = which ? g_bh : g_ah;
    float*  sq = which ? g_sq2 : g_sq1;

    const float4* xr = reinterpret_cast<const float4*>(x + (size_t)row * D_DIM);
    const float4* aj = reinterpret_cast<const float4*>(g_adj);
    const float4* rl = reinterpret_cast<const float4*>(g_rls);

    float ssum = 0.f;
    uint4 packh, packl;
    uint32_t* ph = reinterpret_cast<uint32_t*>(&packh);
    uint32_t* pl = reinterpret_cast<uint32_t*>(&packl);
#pragma unroll
    for (int g = 0; g < 2; g++) {
        int v4 = lane * 2 + g;
        float4 xv = xr[v4];
        float4 av = aj[v4];
        float4 rv = rl[v4];
        float vv[4] = { (xv.x - av.x) * rv.x, (xv.y - av.y) * rv.y,
                        (xv.z - av.z) * rv.z, (xv.w - av.w) * rv.w };
#pragma unroll
        for (int e = 0; e < 4; e += 2) {
            float v0 = vv[e], v1 = vv[e + 1];
            __half h0 = __float2half_rn(v0);
            __half h1 = __float2half_rn(v1);
            __half l0 = __float2half_rn(v0 - __half2float(h0));
            __half l1 = __float2half_rn(v1 - __half2float(h1));
            ph[g * 2 + e / 2] = h2_to_u32(__halves2half2(h0, h1));
            pl[g * 2 + e / 2] = h2_to_u32(__halves2half2(l0, l1));
            ssum = fmaf(v0, v0, ssum);
            ssum = fmaf(v1, v1, ssum);
        }
    }
    reinterpret_cast<uint4*>(hi + (size_t)row * D_DIM)[lane] = packh;
    if (which)
        reinterpret_cast<uint4*>(g_bl + (size_t)row * D_DIM)[lane] = packl;
#pragma unroll
    for (int o = 16; o > 0; o >>= 1)
        ssum += __shfl_xor_sync(0xffffffffu, ssum, o);
    if (lane == 0) sq[row] = ssum;
}

// ============================================================================
// Fused GEMM + Matern epilogue (mma.sync m16n8k16, 2-pass hi/lo)
//
// CTA tile 128x128, 4 warps (2x2), warp tile 64x64, occ 2 (8 warps/SM).
// K = 256 in 8 chunks of 32, cp.async double-buffered.
// Per k16 step: 64 MMAs in 2 passes (ah*bh, ah*bl), both fp32-accumulated
// into the SAME accumulators.  dot = ah*(bh+bl); dropped al*b term gives
// ~3e-4 RMS output error (calibrated model), inside the 1e-3 budget.
// ============================================================================
#define ROW_B    80                    // padded row stride
#define TILE_B   (128 * ROW_B)         // 10240 B per tile
#define STAGE_B  (3 * TILE_B)          // Ah | Bh | Bl = 30720 B
#define SMEM_REQ (2 * STAGE_B + 1536)

__global__ void __launch_bounds__(128, 2)
k_matern_gemm(float* __restrict__ out, int n2) {
    extern __shared__ char smem_raw[];
    uint32_t sbase_u = smem_u32(smem_raw);
    uint32_t abase = (sbase_u + 127u) & ~127u;
    char* ap = smem_raw + (abase - sbase_u);

    const int tid  = threadIdx.x;
    const int lane = tid & 31;
    const int wid  = tid >> 5;
    const int wm   = wid >> 1;   // 0..1 : 64-row slice
    const int wn   = wid & 1;    // 0..1 : 64-col slice
    const int bX   = blockIdx.x;
    const int bY   = blockIdx.y;

    float* s_sq1 = reinterpret_cast<float*>(ap + 2 * STAGE_B);
    float* s_sq2 = reinterpret_cast<float*>(ap + 2 * STAGE_B + 512);
    s_sq1[tid] = g_sq1[(size_t)bY * 128 + tid];
    s_sq2[tid] = g_sq2[(size_t)bX * 128 + tid];

    const __half* __restrict__ pAh = g_ah + (size_t)bY * 128 * D_DIM;
    const __half* __restrict__ pBh = g_bh + (size_t)bX * 128 * D_DIM;
    const __half* __restrict__ pBl = g_bl + (size_t)bX * 128 * D_DIM;

    auto load_stage = [&](int buf, int kc) {
        uint32_t sbuf = abase + (uint32_t)buf * STAGE_B;
        const __half* srcs[3] = { pAh, pBh, pBl };
#pragma unroll
        for (int t3 = 0; t3 < 3; t3++) {
            const __half* src = srcs[t3];
#pragma unroll
            for (int i = 0; i < 4; i++) {
                int idx = tid + i * 128;            // 0..511
                int row = idx >> 2;                 // 0..127
                int g   = idx & 3;                  // 16B group
                uint32_t daddr = sbuf + (uint32_t)t3 * TILE_B
                               + (uint32_t)(row * ROW_B + g * 16);
                cp16(daddr, src + (size_t)row * D_DIM + kc * 32 + g * 8);
            }
        }
    };

    float acc[4][8][4];                 // [mt 16-row][n8 col][4], fp32
#pragma unroll
    for (int i = 0; i < 4; i++)
#pragma unroll
        for (int j = 0; j < 8; j++)
#pragma unroll
            for (int e = 0; e < 4; e++) acc[i][j][e] = 0.f;

    load_stage(0, 0);
    CP_COMMIT();

    const int NCHUNK = D_DIM / 32;   // 8
    for (int c = 0; c < NCHUNK; c++) {
        if (c + 1 < NCHUNK) load_stage((c + 1) & 1, c + 1);
        CP_COMMIT();
        CP_WAIT1();
        __syncthreads();

        uint32_t sA = abase + (uint32_t)(c & 1) * STAGE_B;
        uint32_t sBh = sA + TILE_B;
        uint32_t sBl = sA + 2 * TILE_B;

#pragma unroll
        for (int s = 0; s < 2; s++) {            // two k16 steps per 32-chunk
            // ---- load fragments: A hi (4 LDSM), B hi+lo (8 LDSM) ----
            uint32_t ah[4][4], bh[4][4], bl[4][4];
            int arow = wm * 64 + (lane & 15);
            int ag   = s * 2 + (lane >> 4);
#pragma unroll
            for (int mt = 0; mt < 4; mt++)
                LDSM_X4(ah[mt], sA + (uint32_t)((arow + mt * 16) * ROW_B + ag * 16));
            int t  = lane >> 3;
            int bn = wn * 64 + ((t >> 1) << 3) + (lane & 7);
            int bg = s * 2 + (t & 1);
#pragma unroll
            for (int ng = 0; ng < 4; ng++) {     // 4 n16 groups = 64 cols
                uint32_t boff = (uint32_t)((bn + ng * 16) * ROW_B + bg * 16);
                LDSM_X4(bh[ng], sBh + boff);
                LDSM_X4(bl[ng], sBl + boff);
            }
            // ---- pass 1: ah * bh (32 independent accumulators) ----
#pragma unroll
            for (int mt = 0; mt < 4; mt++)
#pragma unroll
                for (int ng = 0; ng < 4; ng++) {
                    mma16816_f32(acc[mt][ng * 2],     ah[mt], bh[ng]);
                    mma16816_f32(acc[mt][ng * 2 + 1], ah[mt], bh[ng] + 2);
                }
            // ---- pass 2: ah * bl ----
#pragma unroll
            for (int mt = 0; mt < 4; mt++)
#pragma unroll
                for (int ng = 0; ng < 4; ng++) {
                    mma16816_f32(acc[mt][ng * 2],     ah[mt], bl[ng]);
                    mma16816_f32(acc[mt][ng * 2 + 1], ah[mt], bl[ng] + 2);
                }
        }
        __syncthreads();
    }

    // ---- fused Matern epilogue ----
    const int r0 = lane >> 2;
    const int c0 = 2 * (lane & 3);
#pragma unroll
    for (int mt = 0; mt < 4; mt++) {
        int row_l = wm * 64 + mt * 16 + r0;
        int row_g = bY * 128 + row_l;
        float sqa0 = s_sq1[row_l];
        float sqa8 = s_sq1[row_l + 8];
        float* orow0 = out + (size_t)row_g * (size_t)n2 + (size_t)bX * 128;
        float* orow8 = orow0 + 8u * (size_t)n2;
#pragma unroll
        for (int nt = 0; nt < 8; nt++) {
            int col_l = wn * 64 + nt * 8 + c0;
            float sqb0 = s_sq2[col_l];
            float sqb1 = s_sq2[col_l + 1];
            const float* a = acc[mt][nt];
            float sqs[4]  = { sqa0 + sqb0, sqa0 + sqb1, sqa8 + sqb0, sqa8 + sqb1 };
            float res[4];
#pragma unroll
            for (int e = 0; e < 4; e++) {
                float d2 = fmaf(-2.f, a[e], sqs[e]);
                d2 = fmaxf(d2, 1e-30f);
                float t2 = SQRT3F * (d2 * rsqrtf(d2));
                res[e] = (1.f + t2) * __expf(-t2);
            }
            *reinterpret_cast<float2*>(orow0 + col_l) = make_float2(res[0], res[1]);
            *reinterpret_cast<float2*>(orow8 + col_l) = make_float2(res[2], res[3]);
        }
    }
}

// ============================================================================
// kernel_launch
// ============================================================================
extern "C" void kernel_launch(void* const* d_in, const int* in_sizes, int n_in,
                              void* d_out, int out_size) {
    const float* x1 = (const float*)d_in[0];
    const float* x2 = (const float*)d_in[1];
    const float* ls = (const float*)d_in[2];
    float* out = (float*)d_out;

    int d  = in_sizes[2];            // 256
    int n1 = in_sizes[0] / d;        // 8192
    int n2 = in_sizes[1] / d;        // 8192

    k_mean_partial<<<32, D_DIM>>>(x1, n1);
    k_mean_final<<<1, D_DIM>>>(ls, n1);
    k_normalize2<<<(n1 + n2) / 8, 256>>>(x1, x2, n1, n1 + n2);

    static bool attr_set = false;
    if (!attr_set) {
        cudaFuncSetAttribute(k_matern_gemm,
                             cudaFuncAttributeMaxDynamicSharedMemorySize, SMEM_REQ);
        attr_set = true;
    }
    dim3 grid(n2 / 128, n1 / 128);
    k_matern_gemm<<<grid, 128, SMEM_REQ>>>(out, n2);
}

// round 10
// speedup vs baseline: 2.6355x; 1.5649x over previous
#include <cuda_runtime.h>
#include <cuda_fp16.h>
#include <cstdint>

// ============================================================================
// Problem constants (dataset: n1=n2=8192, d=256)
// ============================================================================
#define D_DIM 256
#define N_MAX 8192
#define SQRT3F 1.7320508075688772f

// Scratch (allocation-free rule: __device__ globals)
// Single-pass scheme: dot ~= ah*bh (fp16 rounded operands, fp32 accum).
__device__ __align__(128) __half g_ah[N_MAX * D_DIM];
__device__ __align__(128) __half g_bh[N_MAX * D_DIM];
__device__ __align__(128) float  g_sq1[N_MAX];
__device__ __align__(128) float  g_sq2[N_MAX];
__device__ __align__(128) float  g_part[32 * D_DIM];
__device__ __align__(128) float  g_adj[D_DIM];
__device__ __align__(128) float  g_rls[D_DIM];

__device__ __forceinline__ uint32_t h2_to_u32(__half2 h) {
    union { __half2 h; uint32_t u; } c; c.h = h; return c.u;
}

// ============================================================================
// Portable PTX helpers (sm_80-era ISA only: cp.async / ldmatrix / mma.sync)
// ============================================================================
__device__ __forceinline__ uint32_t smem_u32(const void* p) {
    uint32_t a;
    asm("{ .reg .u64 t; cvta.to.shared.u64 t, %1; cvt.u32.u64 %0, t; }"
        : "=r"(a) : "l"(p));
    return a;
}

__device__ __forceinline__ void cp16(uint32_t dst, const void* src) {
    asm volatile("cp.async.cg.shared.global [%0], [%1], 16;"
                 :: "r"(dst), "l"(src) : "memory");
}
#define CP_COMMIT() asm volatile("cp.async.commit_group;" ::: "memory")
#define CP_WAIT1()  asm volatile("cp.async.wait_group 1;" ::: "memory")

#define LDSM_X4(r, addr) \
    asm volatile("ldmatrix.sync.aligned.m8n8.x4.shared.b16 {%0,%1,%2,%3}, [%4];" \
                 : "=r"((r)[0]), "=r"((r)[1]), "=r"((r)[2]), "=r"((r)[3]) \
                 : "r"(addr))

// fp32-accumulator HMMA
__device__ __forceinline__ void mma16816_f32(float* c, const uint32_t* a,
                                             const uint32_t* b) {
    asm volatile(
        "mma.sync.aligned.m16n8k16.row.col.f32.f16.f16.f32 "
        "{%0,%1,%2,%3}, {%4,%5,%6,%7}, {%8,%9}, {%0,%1,%2,%3};"
        : "+f"(c[0]), "+f"(c[1]), "+f"(c[2]), "+f"(c[3])
        : "r"(a[0]), "r"(a[1]), "r"(a[2]), "r"(a[3]),
          "r"(b[0]), "r"(b[1]));
}

// ============================================================================
// Prep kernels (exactly 3 launches before the GEMM -> ncu -s5 hits the GEMM)
// ============================================================================
__global__ void k_mean_partial(const float* __restrict__ x1, int n1) {
    int d = threadIdx.x, b = blockIdx.x;
    float s = 0.f;
    for (int r = b; r < n1; r += 32) s += x1[(size_t)r * D_DIM + d];
    g_part[b * D_DIM + d] = s;
}

__global__ void k_mean_final(const float* __restrict__ ls, int n1) {
    int d = threadIdx.x;
    float s = 0.f;
#pragma unroll
    for (int b = 0; b < 32; b++) s += g_part[b * D_DIM + d];
    g_adj[d] = s / (float)n1;
    g_rls[d] = 1.0f / ls[d];
}

// Center, scale, round to fp16; row sqnorm from EXACT fp32 values.
// Covers x1 rows [0,n1) and x2 rows [n1,ntot). One warp per row.
__global__ void k_normalize2(const float* __restrict__ x1,
                             const float* __restrict__ x2, int n1, int ntot) {
    int wid  = threadIdx.x >> 5;
    int lane = threadIdx.x & 31;
    int grow = blockIdx.x * 8 + wid;
    if (grow >= ntot) return;

    int which = (grow >= n1);
    int row   = which ? (grow - n1) : grow;
    const float* x = which ? x2 : x1;
    __half* hi = which ? g_bh : g_ah;
    float*  sq = which ? g_sq2 : g_sq1;

    const float4* xr = reinterpret_cast<const float4*>(x + (size_t)row * D_DIM);
    const float4* aj = reinterpret_cast<const float4*>(g_adj);
    const float4* rl = reinterpret_cast<const float4*>(g_rls);

    float ssum = 0.f;
    uint4 packh;
    uint32_t* ph = reinterpret_cast<uint32_t*>(&packh);
#pragma unroll
    for (int g = 0; g < 2; g++) {
        int v4 = lane * 2 + g;
        float4 xv = xr[v4];
        float4 av = aj[v4];
        float4 rv = rl[v4];
        float vv[4] = { (xv.x - av.x) * rv.x, (xv.y - av.y) * rv.y,
                        (xv.z - av.z) * rv.z, (xv.w - av.w) * rv.w };
#pragma unroll
        for (int e = 0; e < 4; e += 2) {
            float v0 = vv[e], v1 = vv[e + 1];
            ph[g * 2 + e / 2] = h2_to_u32(__halves2half2(__float2half_rn(v0),
                                                         __float2half_rn(v1)));
            ssum = fmaf(v0, v0, ssum);
            ssum = fmaf(v1, v1, ssum);
        }
    }
    reinterpret_cast<uint4*>(hi + (size_t)row * D_DIM)[lane] = packh;
#pragma unroll
    for (int o = 16; o > 0; o >>= 1)
        ssum += __shfl_xor_sync(0xffffffffu, ssum, o);
    if (lane == 0) sq[row] = ssum;
}

// ============================================================================
// Fused GEMM + Matern epilogue (mma.sync m16n8k16, single fp16 pass)
//
// CTA tile 128x128, 8 warps (2x4), warp tile 64x32, occ 2 (16 warps/SM).
// K = 256 in 8 chunks of 32, cp.async double-buffered.
// Per k16 step per warp: 6 LDSM (A 4, B 2) + 16 MMA, fp32 accum.
// Error budget (calibrated vs R9 measurement): ~3.6e-4 RMS << 1e-3.
// ============================================================================
#define ROW_B    80                    // padded row stride
#define TILE_B   (128 * ROW_B)         // 10240 B per tile
#define STAGE_B  (2 * TILE_B)          // Ah | Bh = 20480 B
#define SMEM_REQ (2 * STAGE_B + 1536)

__global__ void __launch_bounds__(256, 2)
k_matern_gemm(float* __restrict__ out, int n2) {
    extern __shared__ char smem_raw[];
    uint32_t sbase_u = smem_u32(smem_raw);
    uint32_t abase = (sbase_u + 127u) & ~127u;
    char* ap = smem_raw + (abase - sbase_u);

    const int tid  = threadIdx.x;
    const int lane = tid & 31;
    const int wid  = tid >> 5;
    const int wm   = wid >> 2;   // 0..1 : 64-row slice
    const int wn   = wid & 3;    // 0..3 : 32-col slice
    const int bX   = blockIdx.x;
    const int bY   = blockIdx.y;

    float* s_sq1 = reinterpret_cast<float*>(ap + 2 * STAGE_B);
    float* s_sq2 = reinterpret_cast<float*>(ap + 2 * STAGE_B + 512);
    if (tid < 128) {
        s_sq1[tid] = g_sq1[(size_t)bY * 128 + tid];
        s_sq2[tid] = g_sq2[(size_t)bX * 128 + tid];
    }

    const __half* __restrict__ pAh = g_ah + (size_t)bY * 128 * D_DIM;
    const __half* __restrict__ pBh = g_bh + (size_t)bX * 128 * D_DIM;

    // one k32 chunk: 2 tiles x 512 x 16B segs = 1024 cp16 / 256 thr = 4 each
    auto load_stage = [&](int buf, int kc) {
        uint32_t sbuf = abase + (uint32_t)buf * STAGE_B;
#pragma unroll
        for (int i = 0; i < 2; i++) {
            int idx = tid + i * 256;            // 0..511
            int row = idx >> 2;                 // 0..127
            int g   = idx & 3;                  // 16B group
            uint32_t doff = (uint32_t)(row * ROW_B + g * 16);
            size_t   soff = (size_t)row * D_DIM + kc * 32 + g * 8;
            cp16(sbuf + doff, pAh + soff);
            cp16(sbuf + TILE_B + doff, pBh + soff);
        }
    };

    float acc[4][4][4];                 // [mt 16-row][n8 col][4], fp32
#pragma unroll
    for (int i = 0; i < 4; i++)
#pragma unroll
        for (int j = 0; j < 4; j++)
#pragma unroll
            for (int e = 0; e < 4; e++) acc[i][j][e] = 0.f;

    load_stage(0, 0);
    CP_COMMIT();

    const int NCHUNK = D_DIM / 32;   // 8
    for (int c = 0; c < NCHUNK; c++) {
        if (c + 1 < NCHUNK) load_stage((c + 1) & 1, c + 1);
        CP_COMMIT();
        CP_WAIT1();
        __syncthreads();

        uint32_t sA = abase + (uint32_t)(c & 1) * STAGE_B;
        uint32_t sB = sA + TILE_B;

#pragma unroll
        for (int s = 0; s < 2; s++) {            // two k16 steps per 32-chunk
            uint32_t ah[4][4], bh[2][4];
            int arow = wm * 64 + (lane & 15);
            int ag   = s * 2 + (lane >> 4);
#pragma unroll
            for (int mt = 0; mt < 4; mt++)
                LDSM_X4(ah[mt], sA + (uint32_t)((arow + mt * 16) * ROW_B + ag * 16));
            int t  = lane >> 3;
            int bn = wn * 32 + ((t >> 1) << 3) + (lane & 7);
            int bg = s * 2 + (t & 1);
#pragma unroll
            for (int ng = 0; ng < 2; ng++)
                LDSM_X4(bh[ng], sB + (uint32_t)((bn + ng * 16) * ROW_B + bg * 16));
#pragma unroll
            for (int mt = 0; mt < 4; mt++)
#pragma unroll
                for (int ng = 0; ng < 2; ng++) {
                    mma16816_f32(acc[mt][ng * 2],     ah[mt], bh[ng]);
                    mma16816_f32(acc[mt][ng * 2 + 1], ah[mt], bh[ng] + 2);
                }
        }
        __syncthreads();
    }

    // ---- fused Matern epilogue ----
    const int r0 = lane >> 2;
    const int c0 = 2 * (lane & 3);
#pragma unroll
    for (int mt = 0; mt < 4; mt++) {
        int row_l = wm * 64 + mt * 16 + r0;
        int row_g = bY * 128 + row_l;
        float sqa0 = s_sq1[row_l];
        float sqa8 = s_sq1[row_l + 8];
        float* orow0 = out + (size_t)row_g * (size_t)n2 + (size_t)bX * 128;
        float* orow8 = orow0 + 8u * (size_t)n2;
#pragma unroll
        for (int nt = 0; nt < 4; nt++) {
            int col_l = wn * 32 + nt * 8 + c0;
            float sqb0 = s_sq2[col_l];
            float sqb1 = s_sq2[col_l + 1];
            const float* a = acc[mt][nt];
            float sqs[4]  = { sqa0 + sqb0, sqa0 + sqb1, sqa8 + sqb0, sqa8 + sqb1 };
            float res[4];
#pragma unroll
            for (int e = 0; e < 4; e++) {
                float d2 = fmaf(-2.f, a[e], sqs[e]);
                d2 = fmaxf(d2, 1e-30f);
                float t2 = SQRT3F * (d2 * rsqrtf(d2));
                res[e] = (1.f + t2) * __expf(-t2);
            }
            *reinterpret_cast<float2*>(orow0 + col_l) = make_float2(res[0], res[1]);
            *reinterpret_cast<float2*>(orow8 + col_l) = make_float2(res[2], res[3]);
        }
    }
}

// ============================================================================
// kernel_launch
// ============================================================================
extern "C" void kernel_launch(void* const* d_in, const int* in_sizes, int n_in,
                              void* d_out, int out_size) {
    const float* x1 = (const float*)d_in[0];
    const float* x2 = (const float*)d_in[1];
    const float* ls = (const float*)d_in[2];
    float* out = (float*)d_out;

    int d  = in_sizes[2];            // 256
    int n1 = in_sizes[0] / d;        // 8192
    int n2 = in_sizes[1] / d;        // 8192

    k_mean_partial<<<32, D_DIM>>>(x1, n1);
    k_mean_final<<<1, D_DIM>>>(ls, n1);
    k_normalize2<<<(n1 + n2) / 8, 256>>>(x1, x2, n1, n1 + n2);

    static bool attr_set = false;
    if (!attr_set) {
        cudaFuncSetAttribute(k_matern_gemm,
                             cudaFuncAttributeMaxDynamicSharedMemorySize, SMEM_REQ);
        attr_set = true;
    }
    dim3 grid(n2 / 128, n1 / 128);
    k_matern_gemm<<<grid, 256, SMEM_REQ>>>(out, n2);
}